// round 1
// baseline (speedup 1.0000x reference)
#include <cuda_runtime.h>
#include <math.h>

#define BATCH 4
#define SEQ   2048
#define EMB   1024
#define HEADS 16
#define HD    64
#define MTOT  (BATCH*SEQ)   // 8192

// Scratch (module-static device memory: sanctioned, no runtime allocs)
__device__ float g_q[BATCH*HEADS*SEQ*HD];   // [b,h,s,d]
__device__ float g_kt[BATCH*HEADS*HD*SEQ];  // [b,h,d,s]  (K transposed at projection time)
__device__ float g_v[BATCH*HEADS*SEQ*HD];   // [b,h,s,d]
__device__ float g_attn[MTOT*EMB];          // [b,s,h*d] = [M,E]

// ---------------------------------------------------------------------------
// GEMM: C[m,n] = sum_k A[m,k] * W[n,k] + bias[n]
// mode 0: write g_q as [b,h,s,d]
// mode 1: write g_kt as [b,h,d,s]
// mode 2: write g_v as [b,h,s,d]
// mode 3: A := g_attn, write flat [M,E] to `out`
// Tiles: BM=BN=64, BK=16, 256 threads, 4x4 per thread.
// ---------------------------------------------------------------------------
__global__ __launch_bounds__(256) void gemm_kernel(const float* __restrict__ A,
                                                   const float* __restrict__ W,
                                                   const float* __restrict__ bias,
                                                   float* __restrict__ out,
                                                   int mode)
{
    __shared__ float As[16][65];
    __shared__ float Ws[16][65];

    const float* Aptr = (mode == 3) ? g_attn : A;

    int tid = threadIdx.x;
    int tx = tid & 15;
    int ty = tid >> 4;
    int m0 = blockIdx.y * 64;
    int n0 = blockIdx.x * 64;

    float acc[4][4] = {};

    int lrow = tid >> 2;          // 0..63
    int lk   = (tid & 3) * 4;     // 0,4,8,12

    for (int k0 = 0; k0 < EMB; k0 += 16) {
        float4 a = *(const float4*)&Aptr[(size_t)(m0 + lrow) * EMB + k0 + lk];
        float4 w = *(const float4*)&W[(size_t)(n0 + lrow) * EMB + k0 + lk];
        __syncthreads();
        As[lk + 0][lrow] = a.x; As[lk + 1][lrow] = a.y;
        As[lk + 2][lrow] = a.z; As[lk + 3][lrow] = a.w;
        Ws[lk + 0][lrow] = w.x; Ws[lk + 1][lrow] = w.y;
        Ws[lk + 2][lrow] = w.z; Ws[lk + 3][lrow] = w.w;
        __syncthreads();
        #pragma unroll
        for (int kk = 0; kk < 16; kk++) {
            float av[4], wv[4];
            #pragma unroll
            for (int i = 0; i < 4; i++) av[i] = As[kk][ty * 4 + i];
            #pragma unroll
            for (int j = 0; j < 4; j++) wv[j] = Ws[kk][tx * 4 + j];
            #pragma unroll
            for (int i = 0; i < 4; i++)
                #pragma unroll
                for (int j = 0; j < 4; j++)
                    acc[i][j] += av[i] * wv[j];
        }
    }

    // Epilogue
    #pragma unroll
    for (int i = 0; i < 4; i++) {
        int m = m0 + ty * 4 + i;
        int b = m >> 11;          // m / SEQ
        int s = m & (SEQ - 1);
        int nbase = n0 + tx * 4;
        float4 v4;
        v4.x = acc[i][0] + bias[nbase + 0];
        v4.y = acc[i][1] + bias[nbase + 1];
        v4.z = acc[i][2] + bias[nbase + 2];
        v4.w = acc[i][3] + bias[nbase + 3];
        if (mode == 3) {
            *(float4*)&out[(size_t)m * EMB + nbase] = v4;
        } else {
            int h = nbase >> 6;         // head (BN=64 aligns with HD=64)
            int d = nbase & 63;
            int bh = b * HEADS + h;
            if (mode == 0) {
                *(float4*)&g_q[(((size_t)bh * SEQ) + s) * HD + d] = v4;
            } else if (mode == 2) {
                *(float4*)&g_v[(((size_t)bh * SEQ) + s) * HD + d] = v4;
            } else { // mode 1: K transposed [b,h,d,s]
                float vv[4] = {v4.x, v4.y, v4.z, v4.w};
                #pragma unroll
                for (int j = 0; j < 4; j++)
                    g_kt[((size_t)bh * HD + (d + j)) * SEQ + s] = vv[j];
            }
        }
    }
}

// ---------------------------------------------------------------------------
// Flash attention, fp32. One block = 64 query rows of one (b,h).
// Qs: [q][d]   (scaled by 1/sqrt(D))
// KP: [d][k] while holding K^T tile, then reused as P [q][k]
// Vs: [k][d]
// Thread (ty,tx): q rows ty*4+i ; S cols / O cols tx*4+j.
// Row softmax stats reduce across tx via in-warp shfl (tx = lane bits 0..3).
// ---------------------------------------------------------------------------
__global__ __launch_bounds__(256) void attn_kernel()
{
    __shared__ float Qs[64][64];
    __shared__ float KP[64][64];
    __shared__ float Vs[64][64];

    int tid = threadIdx.x;
    int tx = tid & 15;
    int ty = tid >> 4;
    int bh = blockIdx.y;                  // b*HEADS + h
    int q0 = blockIdx.x * 64;

    const float* qg  = g_q  + (size_t)bh * SEQ * HD;
    const float* ktg = g_kt + (size_t)bh * HD * SEQ;
    const float* vg  = g_v  + (size_t)bh * SEQ * HD;

    const float scale = 0.125f; // 1/sqrt(64)

    // Load Q tile, folding in softmax scale.
    for (int f = tid; f < 1024; f += 256) {
        int r = f >> 4, c4 = (f & 15) * 4;
        float4 qv = *(const float4*)&qg[(size_t)(q0 + r) * HD + c4];
        qv.x *= scale; qv.y *= scale; qv.z *= scale; qv.w *= scale;
        *(float4*)&Qs[r][c4] = qv;
    }

    float m_run[4], l_run[4], acc[4][4];
    #pragma unroll
    for (int i = 0; i < 4; i++) {
        m_run[i] = -1e30f;
        l_run[i] = 0.0f;
        #pragma unroll
        for (int j = 0; j < 4; j++) acc[i][j] = 0.0f;
    }

    for (int kt = 0; kt < SEQ / 64; kt++) {
        int k0 = kt * 64;
        __syncthreads();   // prev iter done reading KP(P)/Vs
        for (int f = tid; f < 1024; f += 256) {
            int r = f >> 4, c4 = (f & 15) * 4;
            // K^T tile: KP[d][k], source g_kt[d][k0+k] contiguous in k
            *(float4*)&KP[r][c4] = *(const float4*)&ktg[(size_t)r * SEQ + k0 + c4];
            // V tile: Vs[k][d]
            *(float4*)&Vs[r][c4] = *(const float4*)&vg[(size_t)(k0 + r) * HD + c4];
        }
        __syncthreads();

        // S = Q * K^T   (s[i][j]: qrow ty*4+i, kcol tx*4+j)
        float s[4][4] = {};
        #pragma unroll 8
        for (int d = 0; d < 64; d++) {
            float4 kv = *(const float4*)&KP[d][tx * 4];
            #pragma unroll
            for (int i = 0; i < 4; i++) {
                float qv = Qs[ty * 4 + i][d];
                s[i][0] += qv * kv.x;
                s[i][1] += qv * kv.y;
                s[i][2] += qv * kv.z;
                s[i][3] += qv * kv.w;
            }
        }

        __syncthreads();   // all threads done reading KP (K^T); safe to write P

        // Online softmax per row
        #pragma unroll
        for (int i = 0; i < 4; i++) {
            float tmax = fmaxf(fmaxf(s[i][0], s[i][1]), fmaxf(s[i][2], s[i][3]));
            #pragma unroll
            for (int off = 8; off >= 1; off >>= 1)
                tmax = fmaxf(tmax, __shfl_xor_sync(0xffffffffu, tmax, off));
            float mnew = fmaxf(m_run[i], tmax);
            float corr = __expf(m_run[i] - mnew);
            m_run[i] = mnew;
            float p0 = __expf(s[i][0] - mnew);
            float p1 = __expf(s[i][1] - mnew);
            float p2 = __expf(s[i][2] - mnew);
            float p3 = __expf(s[i][3] - mnew);
            float rsum = p0 + p1 + p2 + p3;
            #pragma unroll
            for (int off = 8; off >= 1; off >>= 1)
                rsum += __shfl_xor_sync(0xffffffffu, rsum, off);
            l_run[i] = l_run[i] * corr + rsum;
            #pragma unroll
            for (int j = 0; j < 4; j++) acc[i][j] *= corr;
            float4 pv = make_float4(p0, p1, p2, p3);
            *(float4*)&KP[ty * 4 + i][tx * 4] = pv;   // P tile [q][k]
        }
        __syncthreads();

        // acc += P * V   (O cols d = tx*4+j)
        #pragma unroll 8
        for (int kk = 0; kk < 64; kk++) {
            float4 vv = *(const float4*)&Vs[kk][tx * 4];
            #pragma unroll
            for (int i = 0; i < 4; i++) {
                float pp = KP[ty * 4 + i][kk];
                acc[i][0] += pp * vv.x;
                acc[i][1] += pp * vv.y;
                acc[i][2] += pp * vv.z;
                acc[i][3] += pp * vv.w;
            }
        }
    }

    // Write normalized output to g_attn [b,s,h*d]
    int b = bh >> 4;
    int h = bh & 15;
    #pragma unroll
    for (int i = 0; i < 4; i++) {
        float inv = 1.0f / l_run[i];
        int qrow = q0 + ty * 4 + i;
        float4 o;
        o.x = acc[i][0] * inv; o.y = acc[i][1] * inv;
        o.z = acc[i][2] * inv; o.w = acc[i][3] * inv;
        *(float4*)&g_attn[((size_t)b * SEQ + qrow) * EMB + h * HD + tx * 4] = o;
    }
}

// ---------------------------------------------------------------------------
extern "C" void kernel_launch(void* const* d_in, const int* in_sizes, int n_in,
                              void* d_out, int out_size)
{
    const float* x  = (const float*)d_in[0];
    const float* wq = (const float*)d_in[1];
    const float* bq = (const float*)d_in[2];
    const float* wk = (const float*)d_in[3];
    const float* bk = (const float*)d_in[4];
    const float* wv = (const float*)d_in[5];
    const float* bv = (const float*)d_in[6];
    const float* wo = (const float*)d_in[7];
    const float* bo = (const float*)d_in[8];
    float* out = (float*)d_out;

    dim3 gemm_grid(EMB / 64, MTOT / 64);   // (16, 128)
    gemm_kernel<<<gemm_grid, 256>>>(x, wq, bq, nullptr, 0);
    gemm_kernel<<<gemm_grid, 256>>>(x, wk, bk, nullptr, 1);
    gemm_kernel<<<gemm_grid, 256>>>(x, wv, bv, nullptr, 2);

    attn_kernel<<<dim3(SEQ / 64, BATCH * HEADS), 256>>>();

    gemm_kernel<<<gemm_grid, 256>>>(nullptr, wo, bo, out, 3);
}

// round 3
// speedup vs baseline: 2.9064x; 2.9064x over previous
#include <cuda_runtime.h>
#include <cstdint>
#include <math.h>

#define BATCH 4
#define SEQ   2048
#define EMB   1024
#define HEADS 16
#define HD    64
#define MTOT  (BATCH*SEQ)   // 8192

// Scratch (module-static device memory)
__device__ float g_q[BATCH*HEADS*SEQ*HD];   // [b,h,s,d]
__device__ float g_k[BATCH*HEADS*SEQ*HD];   // [b,h,s,d]
__device__ float g_vt[BATCH*HEADS*HD*SEQ];  // [b,h,d,s]  (V transposed at projection)
__device__ float g_attn[MTOT*EMB];          // [b,s,h*d] = [M,E]

// ---------------------------------------------------------------------------
// helpers
// ---------------------------------------------------------------------------
__device__ __forceinline__ uint32_t f2tf32(float x) {
    uint32_t r;
    asm("cvt.rna.tf32.f32 %0, %1;" : "=r"(r) : "f"(x));
    return r;
}

// D += A * B  (m16n8k8, A row-major tf32, B col-major tf32, fp32 accum)
__device__ __forceinline__ void mma8(float c[4],
                                     uint32_t a0, uint32_t a1, uint32_t a2, uint32_t a3,
                                     uint32_t b0, uint32_t b1)
{
    asm("mma.sync.aligned.m16n8k8.row.col.f32.tf32.tf32.f32 "
        "{%0,%1,%2,%3}, {%4,%5,%6,%7}, {%8,%9}, {%0,%1,%2,%3};"
        : "+f"(c[0]), "+f"(c[1]), "+f"(c[2]), "+f"(c[3])
        : "r"(a0), "r"(a1), "r"(a2), "r"(a3), "r"(b0), "r"(b1));
}

// ---------------------------------------------------------------------------
// tf32 tensor-core GEMM: C[m,n] = sum_k A[m,k]*W[n,k] + bias[n]
// Block tile 128x128, K-tile 32, 256 threads = 8 warps (2m x 4n), warp 64x32.
// mode 0: dst g_q [b,h,s,d]; 1: g_k [b,h,s,d]; 2: g_vt [b,h,d,s];
// mode 3: A := g_attn, dst flat [M,E] out.
// ---------------------------------------------------------------------------
__global__ __launch_bounds__(256) void gemm_tc(const float* __restrict__ A,
                                               const float* __restrict__ W,
                                               const float* __restrict__ bias,
                                               float* __restrict__ out,
                                               int mode)
{
    __shared__ uint32_t As[128][40];   // [m][k], pad 40 (160B rows, 16B-aligned)
    __shared__ uint32_t Bs[128][40];   // [n][k]

    const float* Aptr = (mode == 3) ? g_attn : A;

    const int tid  = threadIdx.x;
    const int lane = tid & 31;
    const int wid  = tid >> 5;
    const int g    = lane >> 2;
    const int tig  = lane & 3;
    const int wm   = wid & 1;          // 0..1
    const int wn   = wid >> 1;         // 0..3
    const int m0 = blockIdx.y * 128;
    const int n0 = blockIdx.x * 128;

    float acc[4][4][4] = {};

    for (int kb = 0; kb < EMB; kb += 32) {
        #pragma unroll
        for (int t = 0; t < 4; t++) {
            int lin = tid + t * 256;          // 0..1023
            int row = lin >> 3;
            int c4  = (lin & 7) * 4;
            float4 va = *(const float4*)&Aptr[(size_t)(m0 + row) * EMB + kb + c4];
            uint4 ua;
            ua.x = f2tf32(va.x); ua.y = f2tf32(va.y);
            ua.z = f2tf32(va.z); ua.w = f2tf32(va.w);
            *(uint4*)&As[row][c4] = ua;
            float4 vb = *(const float4*)&W[(size_t)(n0 + row) * EMB + kb + c4];
            uint4 ub;
            ub.x = f2tf32(vb.x); ub.y = f2tf32(vb.y);
            ub.z = f2tf32(vb.z); ub.w = f2tf32(vb.w);
            *(uint4*)&Bs[row][c4] = ub;
        }
        __syncthreads();

        #pragma unroll
        for (int ks = 0; ks < 4; ks++) {
            const int k = ks * 8;
            uint32_t a[4][4], bf[4][2];
            #pragma unroll
            for (int mm = 0; mm < 4; mm++) {
                int r = wm * 64 + mm * 16 + g;
                a[mm][0] = As[r][k + tig];
                a[mm][1] = As[r + 8][k + tig];
                a[mm][2] = As[r][k + tig + 4];
                a[mm][3] = As[r + 8][k + tig + 4];
            }
            #pragma unroll
            for (int nn = 0; nn < 4; nn++) {
                int r = wn * 32 + nn * 8 + g;
                bf[nn][0] = Bs[r][k + tig];
                bf[nn][1] = Bs[r][k + tig + 4];
            }
            #pragma unroll
            for (int mm = 0; mm < 4; mm++)
                #pragma unroll
                for (int nn = 0; nn < 4; nn++)
                    mma8(acc[mm][nn], a[mm][0], a[mm][1], a[mm][2], a[mm][3],
                         bf[nn][0], bf[nn][1]);
        }
        __syncthreads();
    }

    // Epilogue: c-frag (row g / g+8, col 2*tig / +1 within each 16x8 tile)
    #pragma unroll
    for (int mm = 0; mm < 4; mm++) {
        #pragma unroll
        for (int nn = 0; nn < 4; nn++) {
            int row0 = m0 + wm * 64 + mm * 16 + g;
            int col  = n0 + wn * 32 + nn * 8 + 2 * tig;
            float2 bi = *(const float2*)&bias[col];
            float2 v0, v1;
            v0.x = acc[mm][nn][0] + bi.x; v0.y = acc[mm][nn][1] + bi.y;
            v1.x = acc[mm][nn][2] + bi.x; v1.y = acc[mm][nn][3] + bi.y;
            #pragma unroll
            for (int rr = 0; rr < 2; rr++) {
                int row = row0 + rr * 8;
                float2 v = rr ? v1 : v0;
                if (mode == 3) {
                    *(float2*)&out[(size_t)row * EMB + col] = v;
                } else {
                    int b = row >> 11, s = row & (SEQ - 1);
                    int h = col >> 6, d = col & 63;
                    size_t bh = (size_t)(b * HEADS + h);
                    if (mode == 2) {   // V transposed: [b,h,d,s]
                        g_vt[(bh * HD + d)     * SEQ + s] = v.x;
                        g_vt[(bh * HD + d + 1) * SEQ + s] = v.y;
                    } else {
                        float* p = (mode == 0) ? g_q : g_k;
                        *(float2*)&p[(bh * SEQ + s) * HD + d] = v;
                    }
                }
            }
        }
    }
}

// ---------------------------------------------------------------------------
// Flash attention with tf32 mma. 128 threads = 4 warps; block = 64 q-rows of
// one (b,h). Warp w owns q-rows [16w, 16w+16). K-tile = 64 keys per iter.
// KP buffer: holds K tile [k][d], then P tile [q][k] (aliased).
// Vt buffer: V^T tile [d][k] (loaded row-major from g_vt).
// ---------------------------------------------------------------------------
__global__ __launch_bounds__(128) void attn_tc()
{
    __shared__ uint32_t KP[64][72];
    __shared__ uint32_t Vt[64][72];

    const int tid  = threadIdx.x;
    const int lane = tid & 31;
    const int wid  = tid >> 5;
    const int g    = lane >> 2;
    const int tig  = lane & 3;
    const int bh = blockIdx.y;
    const int q0 = blockIdx.x * 64;

    const float* qg  = g_q  + (size_t)bh * SEQ * HD;
    const float* kg  = g_k  + (size_t)bh * SEQ * HD;
    const float* vtg = g_vt + (size_t)bh * HD * SEQ;

    // Stage Q (scaled by 1/8, tf32-rounded) through KP, grab A-fragments.
    for (int it = 0; it < 8; it++) {
        int lin = tid + it * 128;
        int row = lin >> 4, c4 = (lin & 15) * 4;
        float4 qv = *(const float4*)&qg[(size_t)(q0 + row) * HD + c4];
        uint4 u;
        u.x = f2tf32(qv.x * 0.125f); u.y = f2tf32(qv.y * 0.125f);
        u.z = f2tf32(qv.z * 0.125f); u.w = f2tf32(qv.w * 0.125f);
        *(uint4*)&KP[row][c4] = u;
    }
    __syncthreads();

    uint32_t aq[8][4];
    {
        int r = wid * 16 + g;
        #pragma unroll
        for (int ks = 0; ks < 8; ks++) {
            int k = ks * 8;
            aq[ks][0] = KP[r][k + tig];
            aq[ks][1] = KP[r + 8][k + tig];
            aq[ks][2] = KP[r][k + tig + 4];
            aq[ks][3] = KP[r + 8][k + tig + 4];
        }
    }

    float m0r = -1e30f, m1r = -1e30f, l0 = 0.0f, l1 = 0.0f;
    float acc[8][4] = {};   // O accumulator: cols nt*8 + 2tig(+1), rows g / g+8

    for (int kt = 0; kt < SEQ / 64; kt++) {
        const int k0 = kt * 64;
        __syncthreads();   // prev iter's PV reads of KP done; Q frags already in regs
        for (int it = 0; it < 8; it++) {
            int lin = tid + it * 128;
            int row = lin >> 4, c4 = (lin & 15) * 4;
            float4 kv = *(const float4*)&kg[(size_t)(k0 + row) * HD + c4];
            uint4 u;
            u.x = f2tf32(kv.x); u.y = f2tf32(kv.y);
            u.z = f2tf32(kv.z); u.w = f2tf32(kv.w);
            *(uint4*)&KP[row][c4] = u;
            float4 vv = *(const float4*)&vtg[(size_t)row * SEQ + k0 + c4];
            uint4 w;
            w.x = f2tf32(vv.x); w.y = f2tf32(vv.y);
            w.z = f2tf32(vv.z); w.w = f2tf32(vv.w);
            *(uint4*)&Vt[row][c4] = w;
        }
        __syncthreads();

        // S = Q * K^T : sacc[nt] covers kcols [nt*8, nt*8+8)
        float sacc[8][4] = {};
        #pragma unroll
        for (int ks = 0; ks < 8; ks++) {
            int k = ks * 8;
            #pragma unroll
            for (int nt = 0; nt < 8; nt++) {
                uint32_t b0 = KP[nt * 8 + g][k + tig];
                uint32_t b1 = KP[nt * 8 + g][k + tig + 4];
                mma8(sacc[nt], aq[ks][0], aq[ks][1], aq[ks][2], aq[ks][3], b0, b1);
            }
        }
        __syncthreads();   // all warps done reading K tile; safe to write P

        // Online softmax for rows (g) and (g+8) of this warp's strip.
        float t0 = -1e30f, t1 = -1e30f;
        #pragma unroll
        for (int nt = 0; nt < 8; nt++) {
            t0 = fmaxf(t0, fmaxf(sacc[nt][0], sacc[nt][1]));
            t1 = fmaxf(t1, fmaxf(sacc[nt][2], sacc[nt][3]));
        }
        t0 = fmaxf(t0, __shfl_xor_sync(0xffffffffu, t0, 1));
        t0 = fmaxf(t0, __shfl_xor_sync(0xffffffffu, t0, 2));
        t1 = fmaxf(t1, __shfl_xor_sync(0xffffffffu, t1, 1));
        t1 = fmaxf(t1, __shfl_xor_sync(0xffffffffu, t1, 2));

        float mn0 = fmaxf(m0r, t0), mn1 = fmaxf(m1r, t1);
        float c0 = __expf(m0r - mn0), c1 = __expf(m1r - mn1);
        m0r = mn0; m1r = mn1;

        float s0 = 0.0f, s1 = 0.0f;
        const int pr = wid * 16 + g;
        #pragma unroll
        for (int nt = 0; nt < 8; nt++) {
            float e00 = __expf(sacc[nt][0] - mn0);
            float e01 = __expf(sacc[nt][1] - mn0);
            float e10 = __expf(sacc[nt][2] - mn1);
            float e11 = __expf(sacc[nt][3] - mn1);
            s0 += e00 + e01; s1 += e10 + e11;
            uint2 p0; p0.x = f2tf32(e00); p0.y = f2tf32(e01);
            uint2 p1; p1.x = f2tf32(e10); p1.y = f2tf32(e11);
            *(uint2*)&KP[pr][nt * 8 + 2 * tig]     = p0;
            *(uint2*)&KP[pr + 8][nt * 8 + 2 * tig] = p1;
            acc[nt][0] *= c0; acc[nt][1] *= c0;
            acc[nt][2] *= c1; acc[nt][3] *= c1;
        }
        s0 += __shfl_xor_sync(0xffffffffu, s0, 1);
        s0 += __shfl_xor_sync(0xffffffffu, s0, 2);
        s1 += __shfl_xor_sync(0xffffffffu, s1, 1);
        s1 += __shfl_xor_sync(0xffffffffu, s1, 2);
        l0 = l0 * c0 + s0;
        l1 = l1 * c1 + s1;
        __syncwarp();   // P strip written by this warp's lanes, read cross-lane below

        // O += P * V : A = P (own 16-row strip), B = V^T tile
        #pragma unroll
        for (int ks = 0; ks < 8; ks++) {
            int k = ks * 8;
            int r = wid * 16 + g;
            uint32_t a0 = KP[r][k + tig];
            uint32_t a1 = KP[r + 8][k + tig];
            uint32_t a2 = KP[r][k + tig + 4];
            uint32_t a3 = KP[r + 8][k + tig + 4];
            #pragma unroll
            for (int nt = 0; nt < 8; nt++) {
                uint32_t b0 = Vt[nt * 8 + g][k + tig];
                uint32_t b1 = Vt[nt * 8 + g][k + tig + 4];
                mma8(acc[nt], a0, a1, a2, a3, b0, b1);
            }
        }
    }

    // Write O / l to g_attn [b, s, h*64 + d]
    const int b = bh >> 4, h = bh & 15;
    const float i0 = 1.0f / l0, i1 = 1.0f / l1;
    const int r0 = q0 + wid * 16 + g;
    #pragma unroll
    for (int nt = 0; nt < 8; nt++) {
        int col = h * 64 + nt * 8 + 2 * tig;
        float2 o0, o1;
        o0.x = acc[nt][0] * i0; o0.y = acc[nt][1] * i0;
        o1.x = acc[nt][2] * i1; o1.y = acc[nt][3] * i1;
        *(float2*)&g_attn[((size_t)b * SEQ + r0) * EMB + col]     = o0;
        *(float2*)&g_attn[((size_t)b * SEQ + r0 + 8) * EMB + col] = o1;
    }
}

// ---------------------------------------------------------------------------
extern "C" void kernel_launch(void* const* d_in, const int* in_sizes, int n_in,
                              void* d_out, int out_size)
{
    const float* x  = (const float*)d_in[0];
    const float* wq = (const float*)d_in[1];
    const float* bq = (const float*)d_in[2];
    const float* wk = (const float*)d_in[3];
    const float* bk = (const float*)d_in[4];
    const float* wv = (const float*)d_in[5];
    const float* bv = (const float*)d_in[6];
    const float* wo = (const float*)d_in[7];
    const float* bo = (const float*)d_in[8];
    float* out = (float*)d_out;

    dim3 grid(EMB / 128, MTOT / 128);   // (8, 64)
    gemm_tc<<<grid, 256>>>(x, wq, bq, nullptr, 0);
    gemm_tc<<<grid, 256>>>(x, wk, bk, nullptr, 1);
    gemm_tc<<<grid, 256>>>(x, wv, bv, nullptr, 2);

    attn_tc<<<dim3(SEQ / 64, BATCH * HEADS), 128>>>();

    gemm_tc<<<grid, 256>>>(nullptr, wo, bo, out, 3);
}

// round 4
// speedup vs baseline: 4.1548x; 1.4295x over previous
#include <cuda_runtime.h>
#include <cstdint>
#include <math.h>

#define BATCH 4
#define SEQ   2048
#define EMB   1024
#define HEADS 16
#define HD    64
#define MTOT  (BATCH*SEQ)   // 8192

// Scratch
__device__ float g_q[BATCH*HEADS*SEQ*HD];   // [b,h,s,d]
__device__ float g_k[BATCH*HEADS*SEQ*HD];   // [b,h,s,d]
__device__ float g_vt[BATCH*HEADS*HD*SEQ];  // [b,h,d,s]
__device__ float g_attn[MTOT*EMB];          // [M,E]

// ---------------------------------------------------------------------------
__device__ __forceinline__ uint32_t f2tf32(float x) {
    uint32_t r;
    asm("cvt.rna.tf32.f32 %0, %1;" : "=r"(r) : "f"(x));
    return r;
}
__device__ __forceinline__ uint32_t smem_u32(const void* p) {
    uint32_t a;
    asm("{ .reg .u64 t; cvta.to.shared.u64 t, %1; cvt.u32.u64 %0, t; }" : "=r"(a) : "l"(p));
    return a;
}
__device__ __forceinline__ void mma8(float c[4],
                                     uint32_t a0, uint32_t a1, uint32_t a2, uint32_t a3,
                                     uint32_t b0, uint32_t b1)
{
    asm("mma.sync.aligned.m16n8k8.row.col.f32.tf32.tf32.f32 "
        "{%0,%1,%2,%3}, {%4,%5,%6,%7}, {%8,%9}, {%0,%1,%2,%3};"
        : "+f"(c[0]), "+f"(c[1]), "+f"(c[2]), "+f"(c[3])
        : "r"(a0), "r"(a1), "r"(a2), "r"(a3), "r"(b0), "r"(b1));
}
__device__ __forceinline__ void ldsm4(uint32_t r[4], uint32_t addr) {
    asm volatile("ldmatrix.sync.aligned.m8n8.x4.shared.b16 {%0,%1,%2,%3}, [%4];"
        : "=r"(r[0]), "=r"(r[1]), "=r"(r[2]), "=r"(r[3]) : "r"(addr));
}

// ---------------------------------------------------------------------------
// tf32 tensor-core GEMM. Block 128x128, K-tile 32, 256 threads = 8 warps
// (2m x 4n), warp tile 64x32. ldmatrix fragment loads, reg double-buffer.
// ---------------------------------------------------------------------------
#define GST 36   // smem row stride (words): conflict-free LDSM

__global__ __launch_bounds__(256) void gemm_tc(const float* __restrict__ A,
                                               const float* __restrict__ W,
                                               const float* __restrict__ bias,
                                               float* __restrict__ out,
                                               int mode)
{
    __shared__ uint32_t As[128 * GST];
    __shared__ uint32_t Bs[128 * GST];

    const float* Aptr = (mode == 3) ? g_attn : A;

    const int tid  = threadIdx.x;
    const int lane = tid & 31;
    const int wid  = tid >> 5;
    const int g    = lane >> 2;
    const int tig  = lane & 3;
    const int wm   = wid & 1;
    const int wn   = wid >> 1;
    const int m0 = blockIdx.y * 128;
    const int n0 = blockIdx.x * 128;

    const uint32_t as_b = smem_u32(As);
    const uint32_t bs_b = smem_u32(Bs);

    // ldmatrix lane address components
    const int mat = lane >> 3, rw = lane & 7;
    const int a_ro = ((mat & 1) << 3) + rw, a_co = (mat >> 1) << 2;
    const int b_ro = ((mat >> 1) << 3) + rw, b_co = (mat & 1) << 2;

    // staging indices
    const int srow = tid >> 3;          // + t*32
    const int sc4  = (tid & 7) * 4;

    float acc[4][4][4] = {};
    float4 ra[4], rb[4];

    #pragma unroll
    for (int t = 0; t < 4; t++) {
        int row = srow + t * 32;
        ra[t] = *(const float4*)&Aptr[(size_t)(m0 + row) * EMB + sc4];
        rb[t] = *(const float4*)&W[(size_t)(n0 + row) * EMB + sc4];
    }

    for (int kc = 0; kc < EMB / 32; kc++) {
        #pragma unroll
        for (int t = 0; t < 4; t++) {
            int row = srow + t * 32;
            uint4 ua, ub;
            ua.x = f2tf32(ra[t].x); ua.y = f2tf32(ra[t].y);
            ua.z = f2tf32(ra[t].z); ua.w = f2tf32(ra[t].w);
            ub.x = f2tf32(rb[t].x); ub.y = f2tf32(rb[t].y);
            ub.z = f2tf32(rb[t].z); ub.w = f2tf32(rb[t].w);
            *(uint4*)&As[row * GST + sc4] = ua;
            *(uint4*)&Bs[row * GST + sc4] = ub;
        }
        __syncthreads();

        if (kc + 1 < EMB / 32) {
            int kb = (kc + 1) * 32;
            #pragma unroll
            for (int t = 0; t < 4; t++) {
                int row = srow + t * 32;
                ra[t] = *(const float4*)&Aptr[(size_t)(m0 + row) * EMB + kb + sc4];
                rb[t] = *(const float4*)&W[(size_t)(n0 + row) * EMB + kb + sc4];
            }
        }

        #pragma unroll
        for (int ks = 0; ks < 4; ks++) {
            const int k = ks * 8;
            uint32_t af[4][4], bf[4][4];
            #pragma unroll
            for (int mm = 0; mm < 4; mm++)
                ldsm4(af[mm], as_b + 4u * ((wm * 64 + mm * 16 + a_ro) * GST + k + a_co));
            #pragma unroll
            for (int np = 0; np < 2; np++)
                ldsm4(bf[np], bs_b + 4u * ((wn * 32 + np * 16 + b_ro) * GST + k + b_co));
            #pragma unroll
            for (int mm = 0; mm < 4; mm++) {
                #pragma unroll
                for (int nn = 0; nn < 4; nn++) {
                    uint32_t* bp = &bf[nn >> 1][(nn & 1) * 2];
                    mma8(acc[mm][nn], af[mm][0], af[mm][1], af[mm][2], af[mm][3],
                         bp[0], bp[1]);
                }
            }
        }
        __syncthreads();
    }

    #pragma unroll
    for (int mm = 0; mm < 4; mm++) {
        #pragma unroll
        for (int nn = 0; nn < 4; nn++) {
            int row0 = m0 + wm * 64 + mm * 16 + g;
            int col  = n0 + wn * 32 + nn * 8 + 2 * tig;
            float2 bi = *(const float2*)&bias[col];
            #pragma unroll
            for (int rr = 0; rr < 2; rr++) {
                int row = row0 + rr * 8;
                float2 v;
                v.x = acc[mm][nn][rr * 2 + 0] + bi.x;
                v.y = acc[mm][nn][rr * 2 + 1] + bi.y;
                if (mode == 3) {
                    *(float2*)&out[(size_t)row * EMB + col] = v;
                } else {
                    int b = row >> 11, s = row & (SEQ - 1);
                    int h = col >> 6, d = col & 63;
                    size_t bh = (size_t)(b * HEADS + h);
                    if (mode == 2) {
                        g_vt[(bh * HD + d)     * SEQ + s] = v.x;
                        g_vt[(bh * HD + d + 1) * SEQ + s] = v.y;
                    } else {
                        float* p = (mode == 0) ? g_q : g_k;
                        *(float2*)&p[(bh * SEQ + s) * HD + d] = v;
                    }
                }
            }
        }
    }
}

// ---------------------------------------------------------------------------
// Flash attention, tf32 mma + ldmatrix. 128 threads = 4 warps, 64 q-rows per
// block, 64-key tiles. KP: K tile [k][d] then P tile [q][k]; Vt: [d][k].
// ---------------------------------------------------------------------------
#define AST 76   // smem row stride (words): conflict-free LDSM

__global__ __launch_bounds__(128) void attn_tc()
{
    __shared__ uint32_t KP[64 * AST];
    __shared__ uint32_t Vt[64 * AST];

    const int tid  = threadIdx.x;
    const int lane = tid & 31;
    const int wid  = tid >> 5;
    const int g    = lane >> 2;
    const int tig  = lane & 3;
    const int bh = blockIdx.y;
    const int q0 = blockIdx.x * 64;

    const float* qg  = g_q  + (size_t)bh * SEQ * HD;
    const float* kg  = g_k  + (size_t)bh * SEQ * HD;
    const float* vtg = g_vt + (size_t)bh * HD * SEQ;

    const uint32_t kp_b = smem_u32(KP);
    const uint32_t vt_b = smem_u32(Vt);

    const int mat = lane >> 3, rw = lane & 7;
    const int a_ro = ((mat & 1) << 3) + rw, a_co = (mat >> 1) << 2;
    const int b_ro = ((mat >> 1) << 3) + rw, b_co = (mat & 1) << 2;

    // Stage Q (scaled, tf32) then pull A-fragments to registers.
    for (int it = 0; it < 8; it++) {
        int lin = tid + it * 128;
        int row = lin >> 4, c4 = (lin & 15) * 4;
        float4 qv = *(const float4*)&qg[(size_t)(q0 + row) * HD + c4];
        uint4 u;
        u.x = f2tf32(qv.x * 0.125f); u.y = f2tf32(qv.y * 0.125f);
        u.z = f2tf32(qv.z * 0.125f); u.w = f2tf32(qv.w * 0.125f);
        *(uint4*)&KP[row * AST + c4] = u;
    }
    __syncthreads();

    uint32_t aq[8][4];
    #pragma unroll
    for (int ks = 0; ks < 8; ks++)
        ldsm4(aq[ks], kp_b + 4u * ((wid * 16 + a_ro) * AST + ks * 8 + a_co));

    float m0r = -1e30f, m1r = -1e30f, l0 = 0.0f, l1 = 0.0f;
    float acc[8][4] = {};

    for (int kt = 0; kt < SEQ / 64; kt++) {
        const int k0 = kt * 64;
        __syncthreads();
        for (int it = 0; it < 8; it++) {
            int lin = tid + it * 128;
            int row = lin >> 4, c4 = (lin & 15) * 4;
            float4 kv = *(const float4*)&kg[(size_t)(k0 + row) * HD + c4];
            uint4 u;
            u.x = f2tf32(kv.x); u.y = f2tf32(kv.y);
            u.z = f2tf32(kv.z); u.w = f2tf32(kv.w);
            *(uint4*)&KP[row * AST + c4] = u;
            float4 vv = *(const float4*)&vtg[(size_t)row * SEQ + k0 + c4];
            uint4 w;
            w.x = f2tf32(vv.x); w.y = f2tf32(vv.y);
            w.z = f2tf32(vv.z); w.w = f2tf32(vv.w);
            *(uint4*)&Vt[row * AST + c4] = w;
        }
        __syncthreads();

        // S = Q * K^T
        float sacc[8][4] = {};
        #pragma unroll
        for (int ks = 0; ks < 8; ks++) {
            const int k = ks * 8;
            #pragma unroll
            for (int np = 0; np < 4; np++) {
                uint32_t bb[4];
                ldsm4(bb, kp_b + 4u * ((np * 16 + b_ro) * AST + k + b_co));
                mma8(sacc[2 * np],     aq[ks][0], aq[ks][1], aq[ks][2], aq[ks][3], bb[0], bb[1]);
                mma8(sacc[2 * np + 1], aq[ks][0], aq[ks][1], aq[ks][2], aq[ks][3], bb[2], bb[3]);
            }
        }
        __syncthreads();   // all warps done reading K tile

        // Online softmax, rows g and g+8 of own 16-row strip.
        float t0 = -1e30f, t1 = -1e30f;
        #pragma unroll
        for (int nt = 0; nt < 8; nt++) {
            t0 = fmaxf(t0, fmaxf(sacc[nt][0], sacc[nt][1]));
            t1 = fmaxf(t1, fmaxf(sacc[nt][2], sacc[nt][3]));
        }
        t0 = fmaxf(t0, __shfl_xor_sync(0xffffffffu, t0, 1));
        t0 = fmaxf(t0, __shfl_xor_sync(0xffffffffu, t0, 2));
        t1 = fmaxf(t1, __shfl_xor_sync(0xffffffffu, t1, 1));
        t1 = fmaxf(t1, __shfl_xor_sync(0xffffffffu, t1, 2));

        float mn0 = fmaxf(m0r, t0), mn1 = fmaxf(m1r, t1);
        float c0 = __expf(m0r - mn0), c1 = __expf(m1r - mn1);
        m0r = mn0; m1r = mn1;

        float s0 = 0.0f, s1 = 0.0f;
        const int pr = wid * 16 + g;
        #pragma unroll
        for (int nt = 0; nt < 8; nt++) {
            float e00 = __expf(sacc[nt][0] - mn0);
            float e01 = __expf(sacc[nt][1] - mn0);
            float e10 = __expf(sacc[nt][2] - mn1);
            float e11 = __expf(sacc[nt][3] - mn1);
            s0 += e00 + e01; s1 += e10 + e11;
            uint2 p0; p0.x = f2tf32(e00); p0.y = f2tf32(e01);
            uint2 p1; p1.x = f2tf32(e10); p1.y = f2tf32(e11);
            *(uint2*)&KP[pr * AST + nt * 8 + 2 * tig]       = p0;
            *(uint2*)&KP[(pr + 8) * AST + nt * 8 + 2 * tig] = p1;
            acc[nt][0] *= c0; acc[nt][1] *= c0;
            acc[nt][2] *= c1; acc[nt][3] *= c1;
        }
        s0 += __shfl_xor_sync(0xffffffffu, s0, 1);
        s0 += __shfl_xor_sync(0xffffffffu, s0, 2);
        s1 += __shfl_xor_sync(0xffffffffu, s1, 1);
        s1 += __shfl_xor_sync(0xffffffffu, s1, 2);
        l0 = l0 * c0 + s0;
        l1 = l1 * c1 + s1;
        __syncwarp();   // P strip is warp-local

        // O += P * V
        #pragma unroll
        for (int ks = 0; ks < 8; ks++) {
            const int k = ks * 8;
            uint32_t pa[4];
            ldsm4(pa, kp_b + 4u * ((wid * 16 + a_ro) * AST + k + a_co));
            #pragma unroll
            for (int np = 0; np < 4; np++) {
                uint32_t bb[4];
                ldsm4(bb, vt_b + 4u * ((np * 16 + b_ro) * AST + k + b_co));
                mma8(acc[2 * np],     pa[0], pa[1], pa[2], pa[3], bb[0], bb[1]);
                mma8(acc[2 * np + 1], pa[0], pa[1], pa[2], pa[3], bb[2], bb[3]);
            }
        }
    }

    const int b = bh >> 4, h = bh & 15;
    const float i0 = 1.0f / l0, i1 = 1.0f / l1;
    const int r0 = q0 + wid * 16 + g;
    #pragma unroll
    for (int nt = 0; nt < 8; nt++) {
        int col = h * 64 + nt * 8 + 2 * tig;
        float2 o0, o1;
        o0.x = acc[nt][0] * i0; o0.y = acc[nt][1] * i0;
        o1.x = acc[nt][2] * i1; o1.y = acc[nt][3] * i1;
        *(float2*)&g_attn[((size_t)b * SEQ + r0) * EMB + col]     = o0;
        *(float2*)&g_attn[((size_t)b * SEQ + r0 + 8) * EMB + col] = o1;
    }
}

// ---------------------------------------------------------------------------
extern "C" void kernel_launch(void* const* d_in, const int* in_sizes, int n_in,
                              void* d_out, int out_size)
{
    const float* x  = (const float*)d_in[0];
    const float* wq = (const float*)d_in[1];
    const float* bq = (const float*)d_in[2];
    const float* wk = (const float*)d_in[3];
    const float* bk = (const float*)d_in[4];
    const float* wv = (const float*)d_in[5];
    const float* bv = (const float*)d_in[6];
    const float* wo = (const float*)d_in[7];
    const float* bo = (const float*)d_in[8];
    float* out = (float*)d_out;

    dim3 grid(EMB / 128, MTOT / 128);   // (8, 64)
    gemm_tc<<<grid, 256>>>(x, wq, bq, nullptr, 0);
    gemm_tc<<<grid, 256>>>(x, wk, bk, nullptr, 1);
    gemm_tc<<<grid, 256>>>(x, wv, bv, nullptr, 2);

    attn_tc<<<dim3(SEQ / 64, BATCH * HEADS), 128>>>();

    gemm_tc<<<grid, 256>>>(nullptr, wo, bo, out, 3);
}